// round 12
// baseline (speedup 1.0000x reference)
#include <cuda_runtime.h>

#define B_ 32
#define H_ 3
#define M_ 2048
#define D_ 512
#define L_ 32
#define T_ 2049

#define NCHUNK 32
#define CHUNK (M_ / NCHUNK)   // 64 memories per chunk

// Scratch
__device__ float g_logits[B_ * M_];            // raw logits
__device__ float g_opart[B_ * NCHUNK * D_];    // per-chunk weighted val partials (unnormalized)
__device__ float g_cmax[B_ * NCHUNK];          // per-chunk logit max
__device__ float g_csum[B_ * NCHUNK];          // per-chunk exp-sum (rel. to chunk max)

// ---------------------------------------------------------------------------
// u0[b,d] = sum_l B_emb[query[b,l], d] * pos_enc[l, d]
// ---------------------------------------------------------------------------
__global__ void u0_kernel(const int* __restrict__ query,
                          const float* __restrict__ Bemb,
                          const float* __restrict__ pos,
                          float* __restrict__ u) {
    __shared__ int sq[L_];
    int b = blockIdx.x, d = threadIdx.x;
    if (d < L_) sq[d] = query[b * L_ + d];
    __syncthreads();
    float acc = 0.f;
#pragma unroll
    for (int l = 0; l < L_; ++l)
        acc += Bemb[(size_t)sq[l] * D_ + d] * pos[l * D_ + d];
    u[b * D_ + d] = acc;
}

// ---------------------------------------------------------------------------
// logit[b,m] = dot( key[b,hop,m,:] + TA[hop, rt[b,m], :], u[b,:] )
// grid: (M/8, B), block 256 (one warp per row m).  [R4/R7-proven]
// ---------------------------------------------------------------------------
__global__ void __launch_bounds__(256) logits_kernel(int hop,
                              const float* __restrict__ key,
                              const float* __restrict__ TA,
                              const int* __restrict__ rt,
                              const float* __restrict__ u) {
    __shared__ float4 su[D_ / 4];
    int b = blockIdx.y;
    int tid = threadIdx.x;
    if (tid < D_ / 4) su[tid] = ((const float4*)(u + b * D_))[tid];
    __syncthreads();

    int warp = tid >> 5, lane = tid & 31;
    int m = blockIdx.x * 8 + warp;
    int t = rt[b * M_ + m];

    const float4* krow = (const float4*)(key + ((size_t)(b * H_ + hop) * M_ + m) * D_);
    const float4* trow = (const float4*)(TA + ((size_t)hop * T_ + t) * D_);

    float acc = 0.f;
#pragma unroll
    for (int k = 0; k < 4; ++k) {
        int idx = lane + 32 * k;
        float4 kv = __ldcs(krow + idx);
        float4 tv = __ldg(trow + idx);
        float4 uv = su[idx];
        acc += (kv.x + tv.x) * uv.x + (kv.y + tv.y) * uv.y
             + (kv.z + tv.z) * uv.z + (kv.w + tv.w) * uv.w;
    }
#pragma unroll
    for (int o = 16; o; o >>= 1) acc += __shfl_down_sync(0xffffffffu, acc, o);
    if (lane == 0) g_logits[b * M_ + m] = acc;
}

// ---------------------------------------------------------------------------
// Online-softmax outpart: per chunk c,
//   cmax = max_{m in c} logit,  ex_m = exp(logit_m - cmax),  csum = sum ex_m
//   o[b,c,d] = sum_m ex_m * (val[b,hop,m,d] + TC[hop,rt,d])
// grid: (NCHUNK, B), block 256.  [R7/R11-proven]
// ---------------------------------------------------------------------------
__global__ void __launch_bounds__(256) outpartOS_kernel(int hop,
                               const float* __restrict__ val,
                               const float* __restrict__ TC,
                               const int* __restrict__ rt) {
    int b = blockIdx.y, c = blockIdx.x;
    int tid = threadIdx.x;
    int d4 = tid & 127, grp = tid >> 7;

    __shared__ float sl[CHUNK];
    __shared__ float ex[CHUNK];
    __shared__ int   st[CHUNK];
    __shared__ float4 sacc[D_ / 4];

    if (tid < CHUNK) {
        sl[tid] = g_logits[b * M_ + c * CHUNK + tid];
        st[tid] = rt[b * M_ + c * CHUNK + tid];
    }
    __syncthreads();

    if (tid < CHUNK) {
        float cm = sl[0];
#pragma unroll
        for (int i = 1; i < CHUNK; ++i) cm = fmaxf(cm, sl[i]);
        ex[tid] = __expf(sl[tid] - cm);
        if (tid == 0) g_cmax[b * NCHUNK + c] = cm;
    }
    __syncthreads();

    // chunk exp-sum: warp-parallel in the last warp
    if (tid >= 224) {
        int lane = tid & 31;
        float s = ex[lane] + ex[lane + 32];
#pragma unroll
        for (int o = 16; o; o >>= 1) s += __shfl_down_sync(0xffffffffu, s, o);
        if (lane == 0) g_csum[b * NCHUNK + c] = s;
    }

    const float4* vbase  = (const float4*)(val + ((size_t)(b * H_ + hop) * M_ + c * CHUNK) * D_);
    const float4* tcbase = (const float4*)(TC + (size_t)hop * T_ * D_);

    float4 acc = make_float4(0.f, 0.f, 0.f, 0.f);
#pragma unroll 4
    for (int mm = grp; mm < CHUNK; mm += 2) {
        float pm = ex[mm];
        float4 vv = __ldcs(vbase + (size_t)mm * (D_ / 4) + d4);
        float4 tv = __ldg(tcbase + (size_t)st[mm] * (D_ / 4) + d4);
        acc.x += (vv.x + tv.x) * pm;
        acc.y += (vv.y + tv.y) * pm;
        acc.z += (vv.z + tv.z) * pm;
        acc.w += (vv.w + tv.w) * pm;
    }

    if (grp == 1) sacc[d4] = acc;
    __syncthreads();
    if (grp == 0) {
        float4 o = sacc[d4];
        acc.x += o.x; acc.y += o.y; acc.z += o.z; acc.w += o.w;
        ((float4*)(g_opart + ((size_t)b * NCHUNK + c) * D_))[d4] = acc;
    }
}

// ---------------------------------------------------------------------------
// Combine: gmax = max_c cmax; Z = sum_c csum_c*exp(cmax_c-gmax);
//          u[b,d] += ( sum_c o[b,c,d]*exp(cmax_c-gmax) ) / Z
// grid: (B,4), block 256. lane4 = 32 float4-lanes per block, cg = 8 groups
// of 4 chunks per thread, smem tree over groups. float4 loads throughout.
// ---------------------------------------------------------------------------
__global__ void __launch_bounds__(256) combine_kernel(float* __restrict__ u) {
    int b = blockIdx.x, tid = threadIdx.x;
    int lane = tid & 31;                 // float4 lane within block's 32
    int cg = tid >> 5;                   // chunk group 0..7 (4 chunks each)
    int lane4 = blockIdx.y * 32 + lane;  // global float4 lane 0..127

    __shared__ float w[NCHUNK];
    __shared__ float sinvZ;
    __shared__ float4 sred[256];

    if (tid < NCHUNK) {
        float gm = g_cmax[b * NCHUNK];
#pragma unroll
        for (int i = 1; i < NCHUNK; ++i) gm = fmaxf(gm, g_cmax[b * NCHUNK + i]);
        w[tid] = __expf(g_cmax[b * NCHUNK + tid] - gm);
        if (tid == 0) {
            float Z = 0.f;
#pragma unroll
            for (int i = 0; i < NCHUNK; ++i)
                Z += g_csum[b * NCHUNK + i] * __expf(g_cmax[b * NCHUNK + i] - gm);
            sinvZ = 1.f / Z;
        }
    }
    __syncthreads();

    float4 acc = make_float4(0.f, 0.f, 0.f, 0.f);
#pragma unroll
    for (int j = 0; j < 4; ++j) {
        int c = cg * 4 + j;
        float wc = w[c];
        float4 v = ((const float4*)(g_opart + ((size_t)b * NCHUNK + c) * D_))[lane4];
        acc.x += v.x * wc; acc.y += v.y * wc;
        acc.z += v.z * wc; acc.w += v.w * wc;
    }
    sred[tid] = acc;
    __syncthreads();
#pragma unroll
    for (int s = 4; s; s >>= 1) {
        if (cg < s) {
            float4 o = sred[tid + s * 32];
            acc.x += o.x; acc.y += o.y; acc.z += o.z; acc.w += o.w;
            sred[tid] = acc;
        }
        __syncthreads();
    }
    if (cg == 0) {
        float invZ = sinvZ;
        float4* up = (float4*)(u + b * D_) + lane4;
        float4 cur = *up;
        cur.x += acc.x * invZ; cur.y += acc.y * invZ;
        cur.z += acc.z * invZ; cur.w += acc.w * invZ;
        *up = cur;
    }
}

// ---------------------------------------------------------------------------
extern "C" void kernel_launch(void* const* d_in, const int* in_sizes, int n_in,
                              void* d_out, int out_size) {
    const int*   query = (const int*)d_in[0];
    const int*   rt    = (const int*)d_in[1];
    const float* key   = (const float*)d_in[2];
    const float* val   = (const float*)d_in[3];
    const float* Bemb  = (const float*)d_in[4];
    const float* TA    = (const float*)d_in[5];
    const float* TC    = (const float*)d_in[6];
    const float* pos   = (const float*)d_in[7];
    float* u = (float*)d_out;   // [B, D]

    u0_kernel<<<B_, D_>>>(query, Bemb, pos, u);
    for (int hop = 0; hop < H_; ++hop) {
        logits_kernel<<<dim3(M_ / 8, B_), 256>>>(hop, key, TA, rt, u);
        outpartOS_kernel<<<dim3(NCHUNK, B_), 256>>>(hop, val, TC, rt);
        combine_kernel<<<dim3(B_, 4), 256>>>(u);
    }
}